// round 14
// baseline (speedup 1.0000x reference)
#include <cuda_runtime.h>

#define DINL __device__ __forceinline__

namespace {
constexpr int Bn = 32, Sn = 256, En = 256, Hn = 512, Ln = 1024;
constexpr int NBLK = 128, NTHR = 256;
}

__device__ float g_he[Bn * Ln * Hn];        // projected encoder (64 MB)
__device__ float g_WsT[Hn * Hn];            // W_s transposed (1 MB)
__device__ float g_hbuf[2][Bn * Hn];
__device__ float g_c[Bn * Hn];
__device__ float g_att[Bn * Hn];
__device__ float g_pm[NBLK], g_ps[NBLK];
__device__ float g_pctx[NBLK * Hn];
__device__ volatile unsigned g_gen;
__device__ unsigned g_cnt;

struct SC {
    float se[Hn];        // s_e for this block's b
    float hb[Hn];        // staged h(t) for this b
    float es[256];       // raw scores for this chunk
    float wgt[256];      // exp(e - M)
    float red_m[8], red_s[8];
};
union __align__(16) SmemU {
    float xs[32][130];   // gate-phase x chunk, [b][k], 64-bit-pair friendly
    float es[32][132];   // precompute enc chunk, [row][h]
    SC c;
};

DINL void gsync() {
    __threadfence();
    __syncthreads();
    if (threadIdx.x == 0) {
        unsigned target = g_gen + 1u;
        if (atomicAdd(&g_cnt, 1u) == gridDim.x - 1u) {
            g_cnt = 0u;
            __threadfence();
            g_gen = target;
        } else {
            while (g_gen != target) { }
            __threadfence();
        }
    }
    __syncthreads();
}

DINL float wredsum(float v) {
    v += __shfl_xor_sync(0xffffffffu, v, 16);
    v += __shfl_xor_sync(0xffffffffu, v, 8);
    v += __shfl_xor_sync(0xffffffffu, v, 4);
    v += __shfl_xor_sync(0xffffffffu, v, 2);
    v += __shfl_xor_sync(0xffffffffu, v, 1);
    return v;
}

DINL float sigm(float x) { return 1.0f / (1.0f + __expf(-x)); }

DINL void ffma2(unsigned long long& acc, unsigned long long a, unsigned long long b) {
    asm("fma.rn.f32x2 %0, %1, %2, %0;" : "+l"(acc) : "l"(a), "l"(b));
}
DINL unsigned long long packf2(float a, float b) {
    unsigned long long r;
    asm("mov.b64 %0, {%1, %2};" : "=l"(r) : "f"(a), "f"(b));
    return r;
}
DINL float lo2(unsigned long long v) { return __uint_as_float((unsigned)v); }
DINL float hi2(unsigned long long v) { return __uint_as_float((unsigned)(v >> 32)); }

__global__ void __launch_bounds__(NTHR, 1) aas_kernel(
    const float* __restrict__ y,    const float* __restrict__ enc,
    const float* __restrict__ W_ih, const float* __restrict__ b_ih,
    const float* __restrict__ W_hh, const float* __restrict__ b_hh,
    const float* __restrict__ W_s,  const float* __restrict__ b_s,
    const float* __restrict__ W_h,  const float* __restrict__ b_h,
    float* __restrict__ outp)
{
    __shared__ SmemU smu;
    __shared__ float sm_g[4][4][32];

    const int tid  = threadIdx.x;
    const int lane = tid & 31;
    const int w    = tid >> 5;
    const int bid  = blockIdx.x;
    const int gtid = bid * NTHR + tid;

    // ---------------- init state ----------------
    for (int i = gtid; i < Bn * Hn; i += NBLK * NTHR) {
        g_hbuf[0][i] = 0.f; g_hbuf[1][i] = 0.f; g_c[i] = 0.f;
        __stcg(&g_att[i], 0.f);
    }
    // W_s transpose: g_WsT[h][m] = W_s[m][h]
    for (int i = gtid; i < Hn * Hn; i += NBLK * NTHR) {
        const int m = i >> 9, h = i & 511;
        g_WsT[h * Hn + m] = W_s[i];
    }

    // ---------------- precompute h_e = enc @ W_h^T + b_h ----------------
    for (int rg = bid; rg < (Bn * Ln) / 32; rg += NBLK) {
        float acc[64];
#pragma unroll
        for (int kk = 0; kk < 64; kk++) acc[kk] = 0.f;
        const int kbase = w * 64;
        for (int ch = 0; ch < 4; ch++) {
            __syncthreads();
            {
                const int b = tid & 31, kg = tid >> 5;
                const float* src = enc + (rg * 32 + b) * Hn + ch * 128 + kg * 16;
#pragma unroll
                for (int i = 0; i < 4; i++) {
                    float4 v = *(const float4*)(src + i * 4);
                    *(float4*)&smu.es[b][kg * 16 + i * 4] = v;
                }
            }
            __syncthreads();
            for (int h4 = 0; h4 < 128; h4 += 4) {
                const float4 x = *(const float4*)&smu.es[lane][h4];
                const float* wp = W_h + kbase * Hn + ch * 128 + h4;
#pragma unroll
                for (int kk = 0; kk < 64; kk++) {
                    const float4 wv = *(const float4*)(wp + kk * Hn);
                    acc[kk] = fmaf(wv.x, x.x, fmaf(wv.y, x.y,
                              fmaf(wv.z, x.z, fmaf(wv.w, x.w, acc[kk]))));
                }
            }
        }
        float* dst = g_he + (rg * 32 + lane) * Hn + kbase;
#pragma unroll
        for (int kk = 0; kk < 64; kk++) dst[kk] = acc[kk] + b_h[kbase + kk];
    }
    gsync();

    // ==================== time-step loop ====================
#pragma unroll 1
    for (int ts = 0; ts < Sn; ts++) {
        const int cur = ts & 1, nxt = cur ^ 1;

        // ---------- A: gates GEMM (FFMA2) + LSTM cell ----------
        {
            unsigned long long acc0 = 0ull, acc1 = 0ull;
            const int q = w >> 1;
            const int rloc = (w & 1) * 2;
            const int r0 = q * Hn + bid * 4 + rloc;
#pragma unroll 1
            for (int ch = 0; ch < 10; ch++) {
                __syncthreads();
                {   // stage x chunk [b][k]
                    const int bb = tid & 31, kg = tid >> 5;
                    const float* src;
                    if (ch < 2)      src = y + (bb * Sn + ts) * En + ch * 128;
                    else if (ch < 6) src = g_att + bb * Hn + (ch - 2) * 128;
                    else             src = g_hbuf[cur] + bb * Hn + (ch - 6) * 128;
                    src += kg * 16;
#pragma unroll
                    for (int i = 0; i < 4; i++) {
                        float4 v = (ch < 2) ? *(const float4*)(src + i * 4)
                                            : __ldcg((const float4*)(src + i * 4));
                        const int k = kg * 16 + i * 4;
                        *(float2*)&smu.xs[bb][k]     = make_float2(v.x, v.y);
                        *(float2*)&smu.xs[bb][k + 2] = make_float2(v.z, v.w);
                    }
                }
                __syncthreads();
                const float* w0p = (ch < 6) ? W_ih + r0 * 768 + ch * 128
                                            : W_hh + r0 * Hn + (ch - 6) * 128;
                const float* w1p = w0p + ((ch < 6) ? 768 : Hn);
#pragma unroll 8
                for (int g4 = 0; g4 < 32; g4++) {
                    const int kk = g4 * 4;
                    const ulonglong2 wa = *(const ulonglong2*)(w0p + kk);
                    const ulonglong2 wb = *(const ulonglong2*)(w1p + kk);
                    const unsigned long long x01 =
                        *(const unsigned long long*)&smu.xs[lane][kk];
                    const unsigned long long x23 =
                        *(const unsigned long long*)&smu.xs[lane][kk + 2];
                    ffma2(acc0, wa.x, x01); ffma2(acc0, wa.y, x23);
                    ffma2(acc1, wb.x, x01); ffma2(acc1, wb.y, x23);
                }
            }
            __syncthreads();
            sm_g[q][rloc][lane]     = lo2(acc0) + hi2(acc0) + b_ih[r0] + b_hh[r0];
            sm_g[q][rloc + 1][lane] = lo2(acc1) + hi2(acc1) + b_ih[r0 + 1] + b_hh[r0 + 1];
            __syncthreads();
            if (tid < 128) {
                const int j = tid >> 5, bb = tid & 31, u = bid * 4 + j;
                const float ig = sigm(sm_g[0][j][bb]);
                const float fg = sigm(sm_g[1][j][bb]);
                const float gg = tanhf(sm_g[2][j][bb]);
                const float og = sigm(sm_g[3][j][bb]);
                const float c = fmaf(fg, g_c[bb * Hn + u], ig * gg);
                g_c[bb * Hn + u] = c;
                const float h = og * tanhf(c);
                __stcg(&g_hbuf[nxt][bb * Hn + u], h);
                outp[(bb * Sn + ts) * Hn + u] = h;
            }
        }
        gsync();

        // ---------- B+C: s_e (shuffle-free) + two-pass softmax attention ----------
        {
            const int b = bid >> 2, chunk = bid & 3;

            // stage h(t) for this b
            if (tid < 128) {
                float4 hv = __ldcg((const float4*)(g_hbuf[nxt] + b * Hn + tid * 4));
                *(float4*)&smu.c.hb[tid * 4] = hv;
            }
            __syncthreads();

            // s_e[m] = sum_h W_sT[h][m] * hb[h] + b_s[m]; lane owns m0, m0+1
            {
                const int m0 = w * 64 + lane * 2;
                float a0 = 0.f, a1 = 0.f;
#pragma unroll 4
                for (int h = 0; h < Hn; h++) {
                    const float hv = smu.c.hb[h];
                    const float2 wv = *(const float2*)(g_WsT + h * Hn + m0);
                    a0 = fmaf(wv.x, hv, a0);
                    a1 = fmaf(wv.y, hv, a1);
                }
                smu.c.se[m0]     = a0 + b_s[m0];
                smu.c.se[m0 + 1] = a1 + b_s[m0 + 1];
            }
            __syncthreads();

            // pass 1: scores for this warp's 32 rows (independent iterations)
            {
                unsigned long long se2[8];
#pragma unroll
                for (int i = 0; i < 4; i++) {
                    const ulonglong2 p = *(const ulonglong2*)&smu.c.se[i * 128 + lane * 4];
                    se2[2 * i] = p.x; se2[2 * i + 1] = p.y;
                }
                float emax = -1e30f;
                const float* herow = g_he + (b * Ln + chunk * 256 + w * 32) * Hn + lane * 4;
#pragma unroll 2
                for (int li = 0; li < 32; li++) {
                    const float* hp = herow + li * Hn;
                    unsigned long long ea = 0ull, eb = 0ull;
#pragma unroll
                    for (int i = 0; i < 4; i++) {
                        const ulonglong2 hv = *(const ulonglong2*)(hp + i * 128);
                        ffma2(ea, hv.x, se2[2 * i]);
                        ffma2(eb, hv.y, se2[2 * i + 1]);
                    }
                    float e = (lo2(ea) + hi2(ea)) + (lo2(eb) + hi2(eb));
                    e = wredsum(e);
                    emax = fmaxf(emax, e);
                    if (lane == 0) smu.c.es[w * 32 + li] = e;
                }
                if (lane == 0) smu.c.red_m[w] = emax;
            }
            __syncthreads();

            // block max, weights, sum
            {
                float M = smu.c.red_m[0];
#pragma unroll
                for (int w2 = 1; w2 < 8; w2++) M = fmaxf(M, smu.c.red_m[w2]);
                const float wgt = __expf(smu.c.es[tid] - M);
                smu.c.wgt[tid] = wgt;
                const float ssum = wredsum(wgt);
                if (lane == 0) smu.c.red_s[w] = ssum;
                __syncthreads();
                if (tid == 0) {
                    float Sb = 0.f;
#pragma unroll
                    for (int w2 = 0; w2 < 8; w2++) Sb += smu.c.red_s[w2];
                    __stcg(&g_pm[bid], M);
                    __stcg(&g_ps[bid], Sb);
                }
            }

            // pass 2: ctx[h] = sum_li wgt[li] * he[li][h]; lane owns h0, h0+1
            {
                const int h0 = w * 64 + lane * 2;
                const float* hc = g_he + (b * Ln + chunk * 256) * Hn + h0;
                unsigned long long a0 = 0ull, a1 = 0ull, a2 = 0ull, a3 = 0ull;
#pragma unroll 2
                for (int li = 0; li < 256; li += 4) {
                    const unsigned long long w0 = packf2(smu.c.wgt[li],     smu.c.wgt[li]);
                    const unsigned long long w1 = packf2(smu.c.wgt[li + 1], smu.c.wgt[li + 1]);
                    const unsigned long long w2 = packf2(smu.c.wgt[li + 2], smu.c.wgt[li + 2]);
                    const unsigned long long w3 = packf2(smu.c.wgt[li + 3], smu.c.wgt[li + 3]);
                    ffma2(a0, *(const unsigned long long*)(hc + (li + 0) * Hn), w0);
                    ffma2(a1, *(const unsigned long long*)(hc + (li + 1) * Hn), w1);
                    ffma2(a2, *(const unsigned long long*)(hc + (li + 2) * Hn), w2);
                    ffma2(a3, *(const unsigned long long*)(hc + (li + 3) * Hn), w3);
                }
                const float cx = (lo2(a0) + lo2(a1)) + (lo2(a2) + lo2(a3));
                const float cy = (hi2(a0) + hi2(a1)) + (hi2(a2) + hi2(a3));
                __stcg((float2*)(g_pctx + bid * Hn + h0), make_float2(cx, cy));
            }
        }
        gsync();

        // ---------- D: combine 4 chunk-partials -> att ----------
        if (gtid < Bn * Hn) {
            const int b = gtid >> 9, h = gtid & 511;
            float pm[4];
#pragma unroll
            for (int cc = 0; cc < 4; cc++) pm[cc] = __ldcg(&g_pm[b * 4 + cc]);
            const float M = fmaxf(fmaxf(pm[0], pm[1]), fmaxf(pm[2], pm[3]));
            float Sd = 0.f, v = 0.f;
#pragma unroll
            for (int cc = 0; cc < 4; cc++) {
                const float wsc = __expf(pm[cc] - M);
                Sd = fmaf(wsc, __ldcg(&g_ps[b * 4 + cc]), Sd);
                v  = fmaf(wsc, __ldcg(&g_pctx[(b * 4 + cc) * Hn + h]), v);
            }
            const float a = v / Sd;
            __stcg(&g_att[b * Hn + h], a);
            outp[Bn * Sn * Hn + (b * Sn + ts) * Hn + h] = a;
        }
        gsync();
    }
}

extern "C" void kernel_launch(void* const* d_in, const int* in_sizes, int n_in,
                              void* d_out, int out_size) {
    (void)in_sizes; (void)n_in; (void)out_size;
    aas_kernel<<<NBLK, NTHR>>>(
        (const float*)d_in[0], (const float*)d_in[1],
        (const float*)d_in[2], (const float*)d_in[3],
        (const float*)d_in[4], (const float*)d_in[5],
        (const float*)d_in[6], (const float*)d_in[7],
        (const float*)d_in[8], (const float*)d_in[9],
        (float*)d_out);
}